// round 3
// baseline (speedup 1.0000x reference)
// O3onO2 tensor product (eSCN-style) — fused fp32 SIMT kernel, f32x2-packed FMAs.
// Structure: out block lo gets, per input block li, per m<=min(lo,li), a 64x64
// channel GEMM (shared W per path) applied to h-combined component columns.
//
// Grid: (4 output blocks) x (N/32 row tiles). Per CTA:
//   stage x block (coalesced) -> combine to z[k][zc][row] -> register GEMM.
#include <cuda_runtime.h>
#include <cstdint>

#define NROWS 65536
#define TILE_M 32
#define NTHREADS 256

// float offsets inside dynamic smem
#define ZS_OFF 14368            // xs region: 32 rows x 449 (max) = 14368 floats
#define WS_OFF (ZS_OFF + 14336) // zs region: 64 * 7 * 32 = 14336 floats max
#define SMEM_FLOATS (WS_OFF + 64 * 66)
#define SMEM_BYTES (SMEM_FLOATS * 4)

__device__ __forceinline__ constexpr int blk_off(int l) {
    return l == 0 ? 0 : (l == 1 ? 64 : (l == 2 ? 256 : 576));
}

__device__ __forceinline__ unsigned long long pack2(float a, float b) {
    unsigned long long r;
    asm("mov.b64 %0, {%1, %2};" : "=l"(r) : "f"(a), "f"(b));
    return r;
}

__device__ __forceinline__ void fma2(unsigned long long& d,
                                     unsigned long long a,
                                     unsigned long long b) {
    asm("fma.rn.f32x2 %0, %1, %2, %0;" : "+l"(d) : "l"(a), "l"(b));
}

// Process one input block LI, accumulating into acc (all 64 out-ch x NC comps tile).
template <int LO, int LI>
__device__ __forceinline__ void process_block(
    float* sm, const float* __restrict__ x, const float* __restrict__ wts,
    const float* __restrict__ hz, const float* __restrict__ hpg,
    const float* __restrict__ hng, int row0,
    unsigned long long (&acc)[2][2][2 * LO + 1], int rg, int og)
{
    constexpr int L   = 64 * (2 * LI + 1);  // floats per row of this block
    constexpr int XST = L + 1;              // padded smem row stride
    constexpr int MM  = (LO < LI ? LO : LI);
    constexpr int NZ  = 2 * MM + 1;
    constexpr int P   = LO * 4 + LI;        // path index
    const int tid = threadIdx.x;

    // ---- stage raw x block tile (fully contiguous per row -> coalesced) ----
    const float* gx = x + (size_t)row0 * 1024 + blk_off(LI);
    for (int idx = tid; idx < TILE_M * L; idx += NTHREADS) {
        int r = idx / L;
        int j = idx - r * L;
        sm[r * XST + j] = gx[(size_t)r * 1024 + j];
    }
    // ---- stage W transposed: ws[i][o], stride 66 ----
    const float* gw = wts + P * 4096;
    for (int idx = tid; idx < 4096; idx += NTHREADS) {
        int o = idx >> 6, i = idx & 63;
        sm[WS_OFF + i * 66 + o] = gw[idx];
    }
    __syncthreads();  // xs/ws ready; also guarantees previous GEMM done with zs

    // ---- combine: z[k][zc][row] ----
    {
        const float h0 = hz[P];
        float hp[MM > 0 ? MM : 1], hn[MM > 0 ? MM : 1];
#pragma unroll
        for (int m = 0; m < MM; m++) { hp[m] = hpg[P * 3 + m]; hn[m] = hng[P * 3 + m]; }
        for (int it = tid; it < 64 * TILE_M; it += NTHREADS) {
            int k = it >> 5;
            int r = it & 31;
            const float* xb = sm + r * XST + k * (2 * LI + 1) + LI;
            sm[ZS_OFF + (k * NZ + 0) * 32 + r] = h0 * xb[0];
#pragma unroll
            for (int m = 1; m <= MM; m++) {
                float xp = xb[m], xn = xb[-m];
                sm[ZS_OFF + (k * NZ + 2 * m - 1) * 32 + r] = hp[m - 1] * xp + hn[m - 1] * xn;
                sm[ZS_OFF + (k * NZ + 2 * m) * 32 + r]     = hp[m - 1] * xn - hn[m - 1] * xp;
            }
        }
    }
    __syncthreads();

    // ---- GEMM: acc[rowpair][oo][comp] += z * W ----
    const unsigned long long* zb =
        reinterpret_cast<const unsigned long long*>(sm + ZS_OFF);
#pragma unroll 4
    for (int k = 0; k < 64; k++) {
        float2 wv = *(const float2*)(sm + WS_OFF + k * 66 + og * 2);
        unsigned long long w0 = pack2(wv.x, wv.x);
        unsigned long long w1 = pack2(wv.y, wv.y);
#pragma unroll
        for (int zc = 0; zc < NZ; zc++) {
            const int c = (zc == 0) ? LO : ((zc & 1) ? LO + (zc + 1) / 2 : LO - zc / 2);
            const unsigned long long* zk = zb + (k * NZ + zc) * 16 + rg * 2;
            unsigned long long z0 = zk[0];
            unsigned long long z1 = zk[1];
            fma2(acc[0][0][c], z0, w0);
            fma2(acc[0][1][c], z0, w1);
            fma2(acc[1][0][c], z1, w0);
            fma2(acc[1][1][c], z1, w1);
        }
    }
}

template <int LO>
__device__ __forceinline__ void run_oi(
    float* sm, const float* __restrict__ x, const float* __restrict__ wts,
    const float* __restrict__ hz, const float* __restrict__ hpg,
    const float* __restrict__ hng, float* __restrict__ out, int row0)
{
    constexpr int NC = 2 * LO + 1;
    const int tid = threadIdx.x;
    const int rg = tid >> 5;   // warp id = row group (4 rows)
    const int og = tid & 31;   // lane = out-channel group (2 channels)

    unsigned long long acc[2][2][NC];
#pragma unroll
    for (int a = 0; a < 2; a++)
#pragma unroll
        for (int b = 0; b < 2; b++)
#pragma unroll
            for (int c = 0; c < NC; c++) acc[a][b][c] = 0ull;

    process_block<LO, 0>(sm, x, wts, hz, hpg, hng, row0, acc, rg, og);
    process_block<LO, 1>(sm, x, wts, hz, hpg, hng, row0, acc, rg, og);
    process_block<LO, 2>(sm, x, wts, hz, hpg, hng, row0, acc, rg, og);
    process_block<LO, 3>(sm, x, wts, hz, hpg, hng, row0, acc, rg, og);

    // ---- stage output tile in smem (exact global layout), then coalesced store ----
    __syncthreads();
    constexpr int SEG = 64 * NC;
#pragma unroll
    for (int pr = 0; pr < 2; pr++)
#pragma unroll
        for (int oo = 0; oo < 2; oo++)
#pragma unroll
            for (int c = 0; c < NC; c++) {
                unsigned long long v = acc[pr][oo][c];
                float vlo = __uint_as_float((unsigned)(v & 0xffffffffull));
                float vhi = __uint_as_float((unsigned)(v >> 32));
                int r = rg * 4 + pr * 2;
                int o = og * 2 + oo;
                sm[r * SEG + o * NC + c]       = vlo;
                sm[(r + 1) * SEG + o * NC + c] = vhi;
            }
    __syncthreads();
    float* go = out + (size_t)row0 * 1024 + blk_off(LO);
    for (int idx = tid; idx < TILE_M * SEG; idx += NTHREADS) {
        int r = idx / SEG;
        int j = idx - r * SEG;
        go[(size_t)r * 1024 + j] = sm[idx];
    }
}

extern "C" __global__ void __launch_bounds__(NTHREADS, 1)
tp_kernel(const float* __restrict__ x, const float* __restrict__ wts,
          const float* __restrict__ hz, const float* __restrict__ hpg,
          const float* __restrict__ hng, float* __restrict__ out)
{
    extern __shared__ float sm[];
    const int row0 = blockIdx.y * TILE_M;
    switch (blockIdx.x) {
        case 0: run_oi<0>(sm, x, wts, hz, hpg, hng, out, row0); break;
        case 1: run_oi<1>(sm, x, wts, hz, hpg, hng, out, row0); break;
        case 2: run_oi<2>(sm, x, wts, hz, hpg, hng, out, row0); break;
        default: run_oi<3>(sm, x, wts, hz, hpg, hng, out, row0); break;
    }
}

extern "C" void kernel_launch(void* const* d_in, const int* in_sizes, int n_in,
                              void* d_out, int out_size)
{
    const float* x   = (const float*)d_in[0];
    const float* wts = (const float*)d_in[1];
    const float* hz  = (const float*)d_in[2];
    const float* hpg = (const float*)d_in[3];
    const float* hng = (const float*)d_in[4];
    float* out = (float*)d_out;

    cudaFuncSetAttribute(tp_kernel, cudaFuncAttributeMaxDynamicSharedMemorySize,
                         SMEM_BYTES);
    dim3 grid(4, NROWS / TILE_M);
    tp_kernel<<<grid, NTHREADS, SMEM_BYTES>>>(x, wts, hz, hpg, hng, out);
}